// round 2
// baseline (speedup 1.0000x reference)
#include <cuda_runtime.h>

// Problem constants (fixed by setup_inputs)
#define Mdim 32
#define Ndim 4
#define Ldim 2048
#define Hdim 64
#define Kdim 5
#define Gg   10
#define NSTEPS 20

// Tiling
#define LT 256             // spatial tile (out positions per block)
#define NT 256             // threads per block
#define TILES (Ldim / LT)  // 8

// Shared memory layout (in floats)
#define SU_STRIDE (LT + 8)   // u tile row: halo 4 each side -> 264
#define SH_STRIDE (LT + 8)   // h1 tile row: need LT+4=260, pad to 264 (16B aligned)
#define SM_W1 0                               // 64*4*5 = 1280
#define SM_B1 (SM_W1 + Hdim * Ndim * Kdim)    // 1280
#define SM_W2 (SM_B1 + Hdim)                  // 1344
#define SM_B2 (SM_W2 + Ndim * Hdim * Kdim)    // 2624
#define SM_SU (SM_B2 + Ndim)                  // 2628
#define SM_SH (SM_SU + Ndim * SU_STRIDE)      // 3684
#define SM_TOTAL (SM_SH + Hdim * SH_STRIDE)   // 20580 floats = 82320 B

// Scratch state buffers (no cudaMalloc allowed)
__device__ float g_bufA[Mdim * Ndim * Ldim];
__device__ float g_bufB[Mdim * Ndim * Ldim];
__device__ float g_bufC0[Mdim * Ndim * Ldim];
__device__ float g_bufC1[Mdim * Ndim * Ldim];

__device__ __forceinline__ float my_tanh(float x) {
    // tanh(x) = 1 - 2/(exp(2x)+1); __expf ~2ulp, saturates correctly at +/-inf
    float e = __expf(2.0f * x);
    return 1.0f - __fdividef(2.0f, e + 1.0f);
}

// One RK stage: out = bdry(alpha*z + beta*u + gamma*(conv2(tanh(conv1(u)))))
// conv padding is zero-pad ('same', pad=2) on both convs.
__global__ void __launch_bounds__(NT)
stage_kernel(const float* __restrict__ z, const float* __restrict__ u,
             float* __restrict__ out,
             const float* __restrict__ W1, const float* __restrict__ b1,
             const float* __restrict__ W2, const float* __restrict__ b2,
             float alpha, float beta, float gamma)
{
    extern __shared__ float s[];
    const int tid  = threadIdx.x;
    const int m    = blockIdx.y;
    const int base = blockIdx.x * LT;

    // ---- load weights into smem ----
    for (int i = tid; i < Hdim * Ndim * Kdim; i += NT) s[SM_W1 + i] = W1[i];
    for (int i = tid; i < Hdim; i += NT)               s[SM_B1 + i] = b1[i];
    for (int i = tid; i < Ndim * Hdim * Kdim; i += NT) s[SM_W2 + i] = W2[i];
    for (int i = tid; i < Ndim; i += NT)               s[SM_B2 + i] = b2[i];

    // ---- load u tile with halo 4 (zero-padded at domain edges) ----
    for (int i = tid; i < Ndim * SU_STRIDE; i += NT) {
        int ci = i / SU_STRIDE;
        int j  = i - ci * SU_STRIDE;
        int gx = base - 4 + j;
        float v = 0.0f;
        if (gx >= 0 && gx < Ldim) v = u[(m * Ndim + ci) * Ldim + gx];
        s[SM_SU + ci * SU_STRIDE + j] = v;
    }
    __syncthreads();

    // ---- Phase A: h1 = tanh(conv1(u)) for positions [base-2, base+LT+2) ----
    // thread: co = tid>>2 (hidden channel), psub = tid&3; 4 positions per iter.
    {
        const int co   = tid >> 2;
        const int psub = tid & 3;
        float w1r[Ndim][Kdim];
#pragma unroll
        for (int ci = 0; ci < Ndim; ci++)
#pragma unroll
            for (int k = 0; k < Kdim; k++)
                w1r[ci][k] = s[SM_W1 + (co * Ndim + ci) * Kdim + k];
        const float b1c = s[SM_B1 + co];

        // (LT+4)/4 = 65 position-quads
        for (int pb = psub; pb < (LT + 4) / 4; pb += 4) {
            const int pp0 = pb * 4;
            float acc[4] = {b1c, b1c, b1c, b1c};
#pragma unroll
            for (int ci = 0; ci < Ndim; ci++) {
                const float* sup = &s[SM_SU + ci * SU_STRIDE + pp0];
                float4 va = *(const float4*)(sup);
                float4 vb = *(const float4*)(sup + 4);
                float w[8] = {va.x, va.y, va.z, va.w, vb.x, vb.y, vb.z, vb.w};
#pragma unroll
                for (int j = 0; j < 4; j++)
#pragma unroll
                    for (int k = 0; k < Kdim; k++)
                        acc[j] = fmaf(w1r[ci][k], w[j + k], acc[j]);
            }
#pragma unroll
            for (int j = 0; j < 4; j++) {
                int hx = base - 2 + pp0 + j;               // global h1 position
                float v = (hx >= 0 && hx < Ldim) ? my_tanh(acc[j]) : 0.0f;
                s[SM_SH + co * SH_STRIDE + pp0 + j] = v;
            }
        }
    }
    __syncthreads();

    // ---- Phase B: conv2 over h1, combine, fused bdry write ----
    // thread: co = tid&3 (output channel), pg = tid>>2 -> positions [4pg, 4pg+4)
    {
        const int co = tid & 3;
        const int pg = tid >> 2;
        const int p0 = pg * 4;

        float acc[4];
        const float b2c = s[SM_B2 + co];
#pragma unroll
        for (int j = 0; j < 4; j++) acc[j] = b2c;

#pragma unroll 8
        for (int ci = 0; ci < Hdim; ci++) {
            const float* shp = &s[SM_SH + ci * SH_STRIDE + p0];
            float4 va = *(const float4*)(shp);
            float4 vb = *(const float4*)(shp + 4);
            float w[8] = {va.x, va.y, va.z, va.w, vb.x, vb.y, vb.z, vb.w};
            const float* wp = &s[SM_W2 + (co * Hdim + ci) * Kdim];
            float wk[Kdim];
#pragma unroll
            for (int k = 0; k < Kdim; k++) wk[k] = wp[k];
#pragma unroll
            for (int j = 0; j < 4; j++)
#pragma unroll
                for (int k = 0; k < Kdim; k++)
                    acc[j] = fmaf(wk[k], w[j + k], acc[j]);
        }

        const int row = (m * Ndim + co) * Ldim;
        float4 zv = *(const float4*)&z[row + base + p0];
        float4 uv = *(const float4*)&s[SM_SU + co * SU_STRIDE + 4 + p0]; // u interior
        float zz[4] = {zv.x, zv.y, zv.z, zv.w};
        float uu[4] = {uv.x, uv.y, uv.z, uv.w};

#pragma unroll
        for (int j = 0; j < 4; j++) {
            float val = alpha * zz[j] + beta * uu[j] + gamma * acc[j];
            int x = base + p0 + j;
            // fused bdry: periodic ghost refresh, each out element written once
            if (x >= Gg && x < Ldim - Gg)           out[row + x] = val;
            if (x >= Ldim - 2 * Gg && x < Ldim - Gg) out[row + x - (Ldim - 2 * Gg)] = val;
            if (x >= Gg && x < 2 * Gg)              out[row + x + (Ldim - 2 * Gg)] = val;
        }
    }
}

extern "C" void kernel_launch(void* const* d_in, const int* in_sizes, int n_in,
                              void* d_out, int out_size) {
    const float* z0 = (const float*)d_in[0];
    const float* W1 = (const float*)d_in[1];
    const float* b1 = (const float*)d_in[2];
    const float* W2 = (const float*)d_in[3];
    const float* b2 = (const float*)d_in[4];
    float* out = (float*)d_out;

    float *A, *B, *C0, *C1;
    cudaGetSymbolAddress((void**)&A,  g_bufA);
    cudaGetSymbolAddress((void**)&B,  g_bufB);
    cudaGetSymbolAddress((void**)&C0, g_bufC0);
    cudaGetSymbolAddress((void**)&C1, g_bufC1);

    const size_t smem = SM_TOTAL * sizeof(float);
    cudaFuncSetAttribute(stage_kernel, cudaFuncAttributeMaxDynamicSharedMemorySize,
                         (int)smem);

    dim3 grid(TILES, Mdim);
    dim3 blk(NT);

    const float h = 1.0f / (float)NSTEPS;  // t1_t0 = 1 -> h = 0.05

    const float* Z = z0;
    float* cbuf[2] = {C0, C1};
    for (int st = 0; st < NSTEPS; st++) {
        float* zo = (st == NSTEPS - 1) ? out : cbuf[st & 1];
        // k1 = bdry(z + h f(z))
        stage_kernel<<<grid, blk, smem>>>(Z, Z, A, W1, b1, W2, b2,
                                          1.0f, 0.0f, h);
        // k2 = bdry(0.75 z + 0.25 k1 + 0.25 h f(k1))
        stage_kernel<<<grid, blk, smem>>>(Z, A, B, W1, b1, W2, b2,
                                          0.75f, 0.25f, 0.25f * h);
        // z' = bdry(z/3 + 2/3 k2 + 2h/3 f(k2))
        stage_kernel<<<grid, blk, smem>>>(Z, B, zo, W1, b1, W2, b2,
                                          1.0f / 3.0f, 2.0f / 3.0f, (2.0f / 3.0f) * h);
        Z = zo;
    }
}